// round 16
// baseline (speedup 1.0000x reference)
#include <cuda_runtime.h>
#include <cstdint>

#define VOCAB 32000
#define BOS_ID 1
#define BSZ 8
#define SEQLEN 2048

// Per-row majority token, computed by hist_kernel, consumed by patch_kernel.
__device__ int g_pred[BSZ];

// ---------------------------------------------------------------------------
// Branch B: per-row majority. Each thread owns 2 tokens; zeroes only its own
// slots (only PRESENT tokens can win the argmax; all-invalid -> BOS), atomics,
// then reads counts[] back at those same 2 positions. 8 blocks, ~1-2us.
// Runs in PARALLEL with the fill via the forked capture stream.
// ---------------------------------------------------------------------------
__global__ void __launch_bounds__(1024) hist_kernel(const int* __restrict__ ids) {
    extern __shared__ int counts[];
    __shared__ int warp_best[32];

    const int b = blockIdx.x;
    const int t = threadIdx.x;

    const int* row = ids + b * SEQLEN;
    const int v0 = row[t];
    const int v1 = row[t + 1024];
    const bool ok0 = (v0 > BOS_ID);           // valid <=> v!=0 && v!=1 <=> v>1
    const bool ok1 = (v1 > BOS_ID);

    // Zero ONLY the slots that will be used (<=2048 of 32000; dups benign).
    if (ok0) counts[v0] = 0;
    if (ok1) counts[v1] = 0;
    __syncthreads();

    if (ok0) atomicAdd(&counts[v0], 1);
    if (ok1) atomicAdd(&counts[v1], 1);
    __syncthreads();

    // Packed key: (count << 15) | (0x7FFF - v). Higher count wins; equal
    // count -> lower v (argmax tie rule). count<=2048 (12b), v<32000 (15b).
    int best = 0;
    if (ok0) best = (counts[v0] << 15) | (0x7FFF - v0);
    if (ok1) best = max(best, (counts[v1] << 15) | (0x7FFF - v1));

    best = __reduce_max_sync(0xFFFFFFFFu, best);
    if ((t & 31) == 0) warp_best[t >> 5] = best;
    __syncthreads();

    if (t < 32) {
        int wb = __reduce_max_sync(0xFFFFFFFFu, warp_best[t]);
        if (t == 0) {
            int cnt = wb >> 15;
            g_pred[b] = (cnt > 0) ? (0x7FFF - (wb & 0x7FFF)) : BOS_ID;
        }
    }
}

// ---------------------------------------------------------------------------
// Branch A: pure -6.0f broadcast, zero dependencies, zero epilogue.
// 64000 blocks x 256 threads x 8 coalesced STG.128. The proven ~270us stream.
// ---------------------------------------------------------------------------
__global__ void __launch_bounds__(256) fill_kernel(float4* __restrict__ out) {
    const float4 v = make_float4(-6.0f, -6.0f, -6.0f, -6.0f);
    float4* p = out + (long long)blockIdx.x * 2048 + threadIdx.x;
    #pragma unroll
    for (int j = 0; j < 8; j++) p[j * 256] = v;
}

// ---------------------------------------------------------------------------
// Join node: patch +6 at (b, s, pred) for all s. 8 blocks x 1024 threads,
// 2 scattered 4B stores each (16384 total). Depends on BOTH branches.
// ---------------------------------------------------------------------------
__global__ void __launch_bounds__(1024) patch_kernel(float* __restrict__ out) {
    const int b = blockIdx.x;
    const int t = threadIdx.x;
    const int pred = g_pred[b];
    float* base = out + (long long)b * SEQLEN * VOCAB + pred;
    base[(long long)t * VOCAB] = 6.0f;
    base[(long long)(t + 1024) * VOCAB] = 6.0f;
}

// ---------------------------------------------------------------------------
extern "C" void kernel_launch(void* const* d_in, const int* in_sizes, int n_in,
                              void* d_out, int out_size) {
    (void)in_sizes; (void)n_in; (void)out_size;
    const int* ids = (const int*)d_in[0];
    float4* out4 = (float4*)d_out;
    float* outf = (float*)d_out;

    const int smem_bytes = VOCAB * (int)sizeof(int);  // 128000 bytes
    cudaFuncSetAttribute(hist_kernel,
                         cudaFuncAttributeMaxDynamicSharedMemorySize, smem_bytes);

    // Fork a side stream so the captured graph has hist PARALLEL to the fill.
    // Host-side resource creation only (no device memory); the harness calls
    // kernel_launch twice (correctness + capture), so the small leak is benign.
    cudaStream_t s2;
    cudaEvent_t evFork, evJoin;
    cudaStreamCreateWithFlags(&s2, cudaStreamNonBlocking);
    cudaEventCreateWithFlags(&evFork, cudaEventDisableTiming);
    cudaEventCreateWithFlags(&evJoin, cudaEventDisableTiming);

    // Fork: s2 branches off the capture stream.
    cudaEventRecord(evFork, 0);
    cudaStreamWaitEvent(s2, evFork, 0);

    // Branch B (side stream): hist -> g_pred.
    hist_kernel<<<BSZ, 1024, smem_bytes, s2>>>(ids);
    cudaEventRecord(evJoin, s2);

    // Branch A (main stream): dependency-free fill, runs concurrently.
    fill_kernel<<<64000, 256>>>(out4);

    // Join: patch depends on both branches.
    cudaStreamWaitEvent(0, evJoin, 0);
    patch_kernel<<<BSZ, 1024>>>(outf);
}